// round 9
// baseline (speedup 1.0000x reference)
#include <cuda_runtime.h>
#include <cuda_bf16.h>
#include <float.h>
#include <math.h>
#include <stdint.h>

// ---------------- problem constants ----------------
constexpr int   Bn   = 16;
constexpr int   Nn   = 33600;
constexpr int   Cc   = 80;
constexpr int   MAXN = 100;
constexpr float THR  = 0.05f;
constexpr float IOUT = 0.65f;

// histogram constants: bucket = (bits - BASE) >> 14
constexpr unsigned BASE = 0x3D000000u;   // below bits(0.05)=0x3D4CCCCD
constexpr int      HB   = 2560;          // (0x3F800000-BASE)>>14 = 256*10
constexpr int      CAP  = 1024;          // candidate record capacity per batch
constexpr int      SLICES = 8;           // compact CTAs per batch
constexpr int      SLICE_A = Nn / SLICES;        // 4200 anchors
constexpr int      SLICE_V = SLICE_A / 2;        // 2100 uint4 (2 anchors each)

// ---------------- device scratch ----------------
__device__ uint2              g_sl[Bn * Nn];      // {score_bits (0 if <THR), label}
__device__ unsigned           g_hist[Bn * HB];    // zero-init; re-zeroed by k_nms
__device__ int                g_cnt[Bn];          // candidate counters; re-zeroed by k_nms
__device__ unsigned long long g_key[Bn * CAP];    // score_bits<<32 | ~idx
__device__ float4             g_boxr[Bn * CAP];   // decoded box
__device__ int                g_labr[Bn * CAP];   // label

// ---------------- kernel 1: sigmoid + max/argmax + packed store + RED histogram ----------------
__global__ void k_score(const float* __restrict__ cls,
                        const float* __restrict__ obj) {
    int t   = blockIdx.x * blockDim.x + threadIdx.x;
    int a   = t >> 2;          // anchor
    int sub = t & 3;
    if (a >= Bn * Nn) return;

    const float4* p = reinterpret_cast<const float4*>(cls + (size_t)a * Cc + sub * 20);
    float mx = -FLT_MAX;
    int   mi = 0;
#pragma unroll
    for (int i = 0; i < 5; i++) {
        float4 v = __ldcs(&p[i]);          // streaming: no reuse
        int base = sub * 20 + i * 4;
        if (v.x > mx) { mx = v.x; mi = base; }
        if (v.y > mx) { mx = v.y; mi = base + 1; }
        if (v.z > mx) { mx = v.z; mi = base + 2; }
        if (v.w > mx) { mx = v.w; mi = base + 3; }
    }
#pragma unroll
    for (int off = 1; off < 4; off <<= 1) {
        float om  = __shfl_xor_sync(0xffffffffu, mx, off);
        int   omi = __shfl_xor_sync(0xffffffffu, mi, off);
        if (om > mx || (om == mx && omi < mi)) { mx = om; mi = omi; }
    }
    if (sub == 0) {
        float o = __ldcs(&obj[a]);
        float s = (1.0f / (1.0f + __expf(-mx))) * (1.0f / (1.0f + __expf(-o)));
        unsigned bits = 0u;
        if (s >= THR) {
            bits = __float_as_uint(s);
            unsigned bk = (bits - BASE) >> 14;
            if (bk >= (unsigned)HB) bk = HB - 1;
            atomicAdd(&g_hist[(a / Nn) * HB + bk], 1u);   // RED, chip-wide
        }
        g_sl[a] = make_uint2(bits, (unsigned)mi);
    }
}

// intra-warp inclusive suffix sum over 32 lanes
__device__ __forceinline__ unsigned warp_suffix_sum(unsigned v, int lane) {
#pragma unroll
    for (int o = 1; o < 32; o <<= 1) {
        unsigned u = __shfl_down_sync(0xffffffffu, v, o);
        if (lane + o < 32) v += u;
    }
    return v;
}

// ---------------- kernel 2: per-slice threshold scan + compact + decode ----------------
__global__ void __launch_bounds__(256, 4)
k_compact(const float* __restrict__ bbox,
          const float* __restrict__ priors) {
    __shared__ unsigned csum[256];
    __shared__ unsigned wsum[8];
    __shared__ unsigned sTB;

    int b    = blockIdx.x >> 3;
    int s    = blockIdx.x & 7;
    int tid  = threadIdx.x;
    int lane = tid & 31;
    int wid  = tid >> 5;
    const unsigned* hh = g_hist + b * HB;

    // chunk sums: 10 buckets per thread (256*10 = 2560)
    unsigned cs = 0;
#pragma unroll
    for (int i = 0; i < 10; i++) cs += hh[tid * 10 + i];

    // suffix scan over 256 chunk sums
    unsigned suf = warp_suffix_sum(cs, lane);
    if (lane == 0) wsum[wid] = suf;
    __syncthreads();
    if (wid == 0 && lane < 8) {
        unsigned wv = wsum[lane];
#pragma unroll
        for (int o = 1; o < 8; o <<= 1) {
            unsigned u = __shfl_down_sync(0xffu, wv, o);
            if (lane + o < 8) wv += u;
        }
        wsum[lane] = wv;
    }
    if (tid == 0) sTB = 0u;   // doubles as boundary-chunk slot
    __syncthreads();
    unsigned suffTotal = suf + ((wid < 7) ? wsum[wid + 1] : 0u);
    csum[tid] = suffTotal;
    __syncthreads();
    if (suffTotal >= (unsigned)MAXN &&
        (tid == 255 || csum[tid + 1] < (unsigned)MAXN))
        sTB = tid;            // boundary chunk index
    __syncthreads();
    if (tid == 0) {
        int c = (int)sTB;
        int cum = (c < 255) ? (int)csum[c + 1] : 0;
        int bstart = c * 10;
        int bb = bstart + 9;
        for (; bb >= bstart; bb--) {
            cum += (int)hh[bb];
            if (cum >= MAXN) break;
        }
        int bucket = (bb < bstart) ? bstart : bb;
        sTB = BASE + ((unsigned)bucket << 14);
    }
    __syncthreads();
    unsigned TB = sTB;

    // compact + decode this slice
    const uint4* sp = reinterpret_cast<const uint4*>(g_sl + (size_t)b * Nn + s * SLICE_A);
    for (int i = tid; i < SLICE_V; i += 256) {
        uint4 v = sp[i];   // {bits0, lab0, bits1, lab1}
#pragma unroll
        for (int h = 0; h < 2; h++) {
            unsigned bits = h ? v.z : v.x;
            unsigned lab  = h ? v.w : v.y;
            if (bits >= TB) {
                int idx = s * SLICE_A + 2 * i + h;
                int pos = atomicAdd(&g_cnt[b], 1);
                if (pos < CAP) {
                    float4 pr = reinterpret_cast<const float4*>(priors)[idx];
                    float4 bp = reinterpret_cast<const float4*>(bbox)[(size_t)b * Nn + idx];
                    float cx = bp.x * pr.z + pr.x;
                    float cy = bp.y * pr.w + pr.y;
                    float w  = __expf(bp.z) * pr.z;
                    float hh2= __expf(bp.w) * pr.w;
                    g_key[b * CAP + pos]  = ((unsigned long long)bits << 32) | (unsigned)(~idx);
                    g_boxr[b * CAP + pos] = make_float4(cx - 0.5f * w, cy - 0.5f * hh2,
                                                        cx + 0.5f * w, cy + 0.5f * hh2);
                    g_labr[b * CAP + pos] = (int)lab;
                }
            }
        }
    }
}

// ---------------- kernel 3: rank + matrix NMS + write + state rezero ----------------
__global__ void __launch_bounds__(1024, 1)
k_nms(float* __restrict__ out, int write_keep) {
    __shared__ unsigned long long keys[CAP];
    __shared__ int      spos[128];
    __shared__ float4   bx4[MAXN];
    __shared__ float    ars[MAXN];
    __shared__ float    sss[MAXN];
    __shared__ int      lls[MAXN];
    __shared__ unsigned sup[MAXN][4];
    __shared__ unsigned kin[4];
    __shared__ unsigned kout[4];

    int b   = blockIdx.x;
    int tid = threadIdx.x;

    int cnt = g_cnt[b]; if (cnt > CAP) cnt = CAP;
    if (tid < cnt) keys[tid] = g_key[b * CAP + tid];
    if (tid < 128) spos[tid] = -1;
    if (tid < 4)   kin[tid] = 0u;
    __syncthreads();

    // exact rank (keys unique: ~idx in low bits)
    if (tid < cnt) {
        unsigned long long mk = keys[tid];
        int r = 0;
        for (int j = 0; j < cnt; j++) r += (keys[j] > mk);
        if (r < 128) spos[r] = tid;
    }
    __syncthreads();

    // decode winners into smem
    if (tid < MAXN) {
        sup[tid][0] = 0u; sup[tid][1] = 0u; sup[tid][2] = 0u; sup[tid][3] = 0u;
        int p = spos[tid];
        if (p >= 0) {
            float4 bb = g_boxr[b * CAP + p];   // L2-hot
            bx4[tid] = bb;
            ars[tid] = (bb.z - bb.x) * (bb.w - bb.y);
            sss[tid] = __uint_as_float((unsigned)(keys[p] >> 32));
            lls[tid] = g_labr[b * CAP + p];
            atomicOr(&kin[tid >> 5], 1u << (tid & 31));
        } else {
            bx4[tid] = make_float4(0.f, 0.f, 0.f, 0.f);
            ars[tid] = 0.f; sss[tid] = 0.f; lls[tid] = -1;
        }
    }
    __syncthreads();

    // parallel pairwise suppression matrix (r > i, same label, IoU >= thr)
    for (int p = tid; p < MAXN * MAXN; p += 1024) {
        int i = p / MAXN;
        int r = p - i * MAXN;
        if (r > i) {
            int li = lls[i];
            if (li >= 0 && li == lls[r]) {
                float4 bi = bx4[i];
                float4 br = bx4[r];
                float ix1 = fmaxf(br.x, bi.x);
                float iy1 = fmaxf(br.y, bi.y);
                float ix2 = fminf(br.z, bi.z);
                float iy2 = fminf(br.w, bi.w);
                float inter = fmaxf(ix2 - ix1, 0.0f) * fmaxf(iy2 - iy1, 0.0f);
                float uni   = ars[i] + ars[r] - inter;
                if (inter / (uni + 1e-8f) >= IOUT)
                    atomicOr(&sup[i][r >> 5], 1u << (r & 31));
            }
        }
    }
    __syncthreads();

    // greedy scan: software-pipelined register bit logic on one thread
    if (tid == 0) {
        unsigned k0 = kin[0], k1 = kin[1], k2 = kin[2], k3 = kin[3];
        unsigned n0 = sup[0][0], n1 = sup[0][1], n2 = sup[0][2], n3 = sup[0][3];
        for (int i = 0; i < MAXN - 1; i++) {
            unsigned c0 = n0, c1 = n1, c2 = n2, c3 = n3;
            n0 = sup[i + 1][0]; n1 = sup[i + 1][1];
            n2 = sup[i + 1][2]; n3 = sup[i + 1][3];
            unsigned kw = (i < 32) ? k0 : (i < 64) ? k1 : (i < 96) ? k2 : k3;
            if ((kw >> (i & 31)) & 1u) {
                k0 &= ~c0; k1 &= ~c1; k2 &= ~c2; k3 &= ~c3;
            }
        }
        kout[0] = k0; kout[1] = k1; kout[2] = k2; kout[3] = k3;
    }
    __syncthreads();

    // write output
    if (tid < MAXN) {
        bool kept = (kout[tid >> 5] >> (tid & 31)) & 1u;
        float* row = out + ((size_t)b * MAXN + tid) * 6;
        if (kept) {
            float4 bb = bx4[tid];
            row[0] = bb.x; row[1] = bb.y; row[2] = bb.z; row[3] = bb.w;
            row[4] = sss[tid]; row[5] = (float)lls[tid];
        } else {
            row[0] = 0.0f; row[1] = 0.0f; row[2] = 0.0f; row[3] = 0.0f;
            row[4] = 0.0f; row[5] = -1.0f;
        }
        if (write_keep)
            out[(size_t)Bn * MAXN * 6 + b * MAXN + tid] = kept ? 1.0f : 0.0f;
    }

    // re-zero per-batch state for the next graph replay
    unsigned* hh = g_hist + b * HB;
    for (int i = tid; i < HB; i += 1024) hh[i] = 0u;
    if (tid == 0) g_cnt[b] = 0;
}

// ---------------- host launcher ----------------
extern "C" void kernel_launch(void* const* d_in, const int* in_sizes, int n_in,
                              void* d_out, int out_size) {
    const float* cls    = nullptr;
    const float* bbox   = nullptr;
    const float* obj    = nullptr;
    const float* priors = nullptr;
    for (int i = 0; i < n_in; i++) {
        int sz = in_sizes[i];
        if      (sz == Bn * Nn * Cc) cls    = (const float*)d_in[i];
        else if (sz == Bn * Nn * 4)  bbox   = (const float*)d_in[i];
        else if (sz == Bn * Nn)      obj    = (const float*)d_in[i];
        else if (sz == Nn * 4)       priors = (const float*)d_in[i];
    }
    float* out = (float*)d_out;
    int write_keep = (out_size >= Bn * MAXN * 6 + Bn * MAXN) ? 1 : 0;

    int total_threads = Bn * Nn * 4;
    k_score<<<(total_threads + 255) / 256, 256>>>(cls, obj);
    k_compact<<<Bn * SLICES, 256>>>(bbox, priors);
    k_nms<<<Bn, 1024>>>(out, write_keep);
}